// round 16
// baseline (speedup 1.0000x reference)
#include <cuda_runtime.h>
#include <cuda_bf16.h>
#include <cstdint>
#include <cstddef>

#define H 2048
#define NACT 64
#define STEPS 32
#define NLAYERS 2

#define NSTG 4                      // smem ring depth
#define STG_BYTES 16384
#define CELL_DSM (NSTG * STG_BYTES + 2048 * 4 + 8 * 16 * 4)   // ring + sv + spart

// ---------------- device state ----------------
__device__ __align__(16) float g_h[2][NLAYERS][H];   // [parity][layer]
__device__ __align__(16) float g_c[NLAYERS][H];
__device__ __align__(16) float g_x[H];
__device__ __align__(16) float g_part[2][NACT];      // head partial dots
__device__ float g_logp_sum;
__device__ int   g_action;
__device__ int   g_done;

// bf16 weights, HMMA-fragment-ready (validated R9/R11/R12/R14):
// unit u (16B): lane=u&31, c=(u>>5)&255, T=(u>>13)&511, l=u>>22.
// Tile T covers rows' 16T..16T+15, row' = j*4+gate; chunk c covers concat-k
// 16c..16c+15 (k<2048: W_ih, else W_hh). The 16B is the exact m16n8k16
// A-fragment at offset lane*16. Tile = 128KB contiguous; stage s = chunks
// 32s..32s+31 = bytes [s*16384, (s+1)*16384).
__device__ __align__(16) unsigned char g_wbf[(size_t)NLAYERS * 2 * 4 * H * H * 2];

// ---------------- threefry2x32-20 (bit-exact JAX core) ----------------
__device__ __forceinline__ uint32_t rotl32(uint32_t v, int d) {
    return (v << d) | (v >> (32 - d));
}
__device__ __forceinline__ void threefry2x32(uint32_t k0, uint32_t k1,
                                             uint32_t x0, uint32_t x1,
                                             uint32_t& o0, uint32_t& o1) {
    const uint32_t ks2 = k0 ^ k1 ^ 0x1BD11BDAu;
    x0 += k0; x1 += k1;
    x0 += x1; x1 = rotl32(x1, 13); x1 ^= x0;
    x0 += x1; x1 = rotl32(x1, 15); x1 ^= x0;
    x0 += x1; x1 = rotl32(x1, 26); x1 ^= x0;
    x0 += x1; x1 = rotl32(x1, 6);  x1 ^= x0;
    x0 += k1; x1 += ks2 + 1u;
    x0 += x1; x1 = rotl32(x1, 17); x1 ^= x0;
    x0 += x1; x1 = rotl32(x1, 29); x1 ^= x0;
    x0 += x1; x1 = rotl32(x1, 16); x1 ^= x0;
    x0 += x1; x1 = rotl32(x1, 24); x1 ^= x0;
    x0 += ks2; x1 += k0 + 2u;
    x0 += x1; x1 = rotl32(x1, 13); x1 ^= x0;
    x0 += x1; x1 = rotl32(x1, 15); x1 ^= x0;
    x0 += x1; x1 = rotl32(x1, 26); x1 ^= x0;
    x0 += x1; x1 = rotl32(x1, 6);  x1 ^= x0;
    x0 += k0; x1 += k1 + 3u;
    x0 += x1; x1 = rotl32(x1, 17); x1 ^= x0;
    x0 += x1; x1 = rotl32(x1, 29); x1 ^= x0;
    x0 += x1; x1 = rotl32(x1, 16); x1 ^= x0;
    x0 += x1; x1 = rotl32(x1, 24); x1 ^= x0;
    x0 += k1; x1 += ks2 + 4u;
    x0 += x1; x1 = rotl32(x1, 13); x1 ^= x0;
    x0 += x1; x1 = rotl32(x1, 15); x1 ^= x0;
    x0 += x1; x1 = rotl32(x1, 26); x1 ^= x0;
    x0 += x1; x1 = rotl32(x1, 6);  x1 ^= x0;
    x0 += ks2; x1 += k0 + 5u;
    o0 = x0; o1 = x1;
}
__device__ __forceinline__ float jax_uniform(uint32_t bits) {
    const float tiny = 1.1754943508222875e-38f;
    uint32_t fb = (bits >> 9) | 0x3f800000u;
    float u = __uint_as_float(fb) - 1.0f;
    u = u * 1.0f + tiny;
    return fmaxf(tiny, u);
}
__device__ __forceinline__ uint32_t bf2_bits(float a, float b) {
    __nv_bfloat162 v = __floats2bfloat162_rn(a, b);
    return *reinterpret_cast<uint32_t*>(&v);
}

// ---------------- weight convert: fp32 -> HMMA-fragment bf16 tiles ----------------
__global__ void convert_kernel(const float* __restrict__ w_ih,
                               const float* __restrict__ w_hh) {
    const size_t NU = (size_t)NLAYERS * 512 * 256 * 32;   // 16B units
    size_t stride = (size_t)gridDim.x * blockDim.x;
    for (size_t u = (size_t)blockIdx.x * blockDim.x + threadIdx.x; u < NU; u += stride) {
        int lane = (int)(u & 31);
        int c    = (int)((u >> 5) & 255);
        int T    = (int)((u >> 13) & 511);
        int l    = (int)(u >> 22);
        int gid  = lane >> 2, t4 = lane & 3;
        int k0c  = 16 * c + 2 * t4;            // concat-k
        int which = k0c >> 11;                  // 0: W_ih, 1: W_hh
        int kk   = k0c & 2047;
        const float* W = (which ? w_hh : w_ih) + (size_t)l * 4 * H * H;
        int rl0 = gid, rl1 = gid + 8;
        int j0 = 4 * T + (rl0 >> 2), g0 = rl0 & 3;
        int j1 = 4 * T + (rl1 >> 2), g1 = rl1 & 3;
        const float* r0p = W + ((size_t)g0 * H + j0) * H;
        const float* r1p = W + ((size_t)g1 * H + j1) * H;
        uint4 o;
        o.x = bf2_bits(r0p[kk],     r0p[kk + 1]);
        o.y = bf2_bits(r1p[kk],     r1p[kk + 1]);
        o.z = bf2_bits(r0p[kk + 8], r0p[kk + 9]);
        o.w = bf2_bits(r1p[kk + 8], r1p[kk + 9]);
        reinterpret_cast<uint4*>(g_wbf)[u] = o;
    }
}

// ---------------- init ----------------
__global__ void init_kernel(const float* __restrict__ start_token) {
    int i = blockIdx.x * blockDim.x + threadIdx.x;
    if (i < H) {
        g_x[i] = start_token[i];
        g_c[0][i] = 0.f; g_c[1][i] = 0.f;
        g_h[0][0][i] = 0.f; g_h[0][1][i] = 0.f;
        g_h[1][0][i] = 0.f; g_h[1][1][i] = 0.f;
        if (i == 0) { g_logp_sum = 0.f; g_action = 0; g_done = 0; }
    }
}

#define CP_ASYNC_16(smem_u32, gptr) \
    asm volatile("cp.async.cg.shared.global [%0], [%1], 16;" \
                 :: "r"(smem_u32), "l"(gptr) : "memory")
#define CP_COMMIT() asm volatile("cp.async.commit_group;" ::: "memory")

// ---------------- HMMA LSTM cell, 4-deep cp.async pipeline ----------------
// grid = 512 blocks x 256 threads (8 warps). Block = tile T (16 rows' = 4 j x
// 4 gates, K=4096 = 128 KB). 8 stages x 16 KB through a 4-stage dynamic-smem
// ring; wait_group 2 keeps 2-3 stages permanently in flight. Warp w consumes
// chunks 4w..4w+3 of each stage. 8 partials reduced in smem; 4 threads fuse.
__global__ void __launch_bounds__(256)
cell_kernel(const float* __restrict__ bih, const float* __restrict__ bhh,
            int layer, int t) {
    extern __shared__ __align__(16) unsigned char dsm[];
    unsigned char* ring = dsm;                                 // NSTG * 16KB
    uint32_t* sv = reinterpret_cast<uint32_t*>(dsm + NSTG * STG_BYTES);  // 8KB
    float* spart = reinterpret_cast<float*>(dsm + NSTG * STG_BYTES + 8192);

    const int tid  = threadIdx.x;
    const int wid  = tid >> 5;
    const int lane = tid & 31;
    const int par_in  = t & 1;
    const int par_out = (t + 1) & 1;
    const int T = blockIdx.x;

    const unsigned char* wt = g_wbf + (size_t)(layer * 512 + T) * 131072;

    // prologue: issue stages 0..2 (fire-and-forget, 3 groups in flight)
#pragma unroll
    for (int p = 0; p < 3; p++) {
        uint32_t sp = (uint32_t)__cvta_generic_to_shared(
            ring + p * STG_BYTES + tid * 16);
        const unsigned char* gp = wt + (size_t)p * STG_BYTES + tid * 16;
#pragma unroll
        for (int i = 0; i < 4; i++)
            CP_ASYNC_16(sp + i * 4096, gp + (size_t)i * 4096);
        CP_COMMIT();
    }

    // stage concat vector while loads are in flight
    {
        const float2* vx = reinterpret_cast<const float2*>(
            (layer == 0) ? g_x : g_h[par_out][0]);
        const float2* vh = reinterpret_cast<const float2*>(g_h[par_in][layer]);
#pragma unroll
        for (int q = tid; q < 2048; q += 256) {
            float2 f = (q < 1024) ? vx[q] : vh[q - 1024];
            sv[q] = bf2_bits(f.x, f.y);
        }
    }

    const int t4 = lane & 3, gid = lane >> 2;
    float c0 = 0.f, c1 = 0.f, c2 = 0.f, c3 = 0.f;

    for (int s = 0; s < 8; s++) {
        // stage s complete when pending groups drop to (committed - s - 1)
        if (s <= 5)      asm volatile("cp.async.wait_group 2;" ::: "memory");
        else if (s == 6) asm volatile("cp.async.wait_group 1;" ::: "memory");
        else             asm volatile("cp.async.wait_group 0;" ::: "memory");
        __syncthreads();   // stage s visible to all warps

        const unsigned char* buf = ring + (s & (NSTG - 1)) * STG_BYTES;
#pragma unroll
        for (int i = 0; i < 4; i++) {
            const int q = 4 * wid + i;              // chunk within stage
            uint4 a = *reinterpret_cast<const uint4*>(buf + q * 512 + lane * 16);
            const int c = s * 32 + q;               // global chunk
            uint32_t b0 = sv[8 * c + t4];
            uint32_t b1 = sv[8 * c + 4 + t4];
            asm volatile(
                "mma.sync.aligned.m16n8k16.row.col.f32.bf16.bf16.f32 "
                "{%0,%1,%2,%3}, {%4,%5,%6,%7}, {%8,%9}, {%0,%1,%2,%3};"
                : "+f"(c0), "+f"(c1), "+f"(c2), "+f"(c3)
                : "r"(a.x), "r"(a.y), "r"(a.z), "r"(a.w), "r"(b0), "r"(b1));
        }
        __syncthreads();   // all warps done with buffer slot before refill

        if (s + 3 < 8) {
            // refill slot (s+3)&3 (= stage s-1's slot, safely consumed)
            uint32_t sn = (uint32_t)__cvta_generic_to_shared(
                ring + ((s + 3) & (NSTG - 1)) * STG_BYTES + tid * 16);
            const unsigned char* gp = wt + (size_t)(s + 3) * STG_BYTES + tid * 16;
#pragma unroll
            for (int i = 0; i < 4; i++)
                CP_ASYNC_16(sn + i * 4096, gp + (size_t)i * 4096);
            CP_COMMIT();
        }
    }

    // C columns all equal: c0 = row' gid partial, c2 = row' gid+8 partial.
    if (t4 == 0) {
        spart[wid * 16 + gid]     = c0;
        spart[wid * 16 + gid + 8] = c2;
    }
    __syncthreads();

    if (tid < 4) {
        const int j = 4 * T + tid;
        float gate[4];
#pragma unroll
        for (int gt = 0; gt < 4; gt++) {
            const int rl = tid * 4 + gt;
            float s = 0.f;
#pragma unroll
            for (int k = 0; k < 8; k++) s += spart[k * 16 + rl];
            gate[gt] = s;
        }
        float gi = gate[0] + bih[j]         + bhh[j];
        float gf = gate[1] + bih[H + j]     + bhh[H + j];
        float gg = gate[2] + bih[2 * H + j] + bhh[2 * H + j];
        float go = gate[3] + bih[3 * H + j] + bhh[3 * H + j];
        float i_ = 1.0f / (1.0f + expf(-gi));
        float f_ = 1.0f / (1.0f + expf(-gf));
        float g_ = tanhf(gg);
        float o_ = 1.0f / (1.0f + expf(-go));
        float cn = f_ * g_c[layer][j] + i_ * g_;
        g_c[layer][j] = cn;
        g_h[par_out][layer][j] = o_ * tanhf(cn);
    }
}

// ---------------- fused head + sample ----------------
__global__ void __launch_bounds__(256)
head_sample_kernel(const float* __restrict__ hw, const float* __restrict__ hb,
                   const float* __restrict__ action_emb,
                   int t, float* __restrict__ out, int out_size) {
    const int r    = blockIdx.x & (NACT - 1);
    const int half = blockIdx.x >> 6;
    const int tid  = threadIdx.x;
    const int par_out = (t + 1) & 1;

    {
        const float4* row = reinterpret_cast<const float4*>(hw + (size_t)r * H);
        const float4* v4  = reinterpret_cast<const float4*>(g_h[par_out][1]);
        int k = half * 256 + tid;
        float4 a = row[k];
        float4 b = v4[k];
        float s = a.x * b.x + a.y * b.y + a.z * b.z + a.w * b.w;
#pragma unroll
        for (int o = 16; o; o >>= 1) s += __shfl_xor_sync(0xffffffffu, s, o);
        __shared__ float sm[8];
        if ((tid & 31) == 0) sm[tid >> 5] = s;
        __syncthreads();
        if (tid == 0) {
            g_part[half][r] = sm[0] + sm[1] + sm[2] + sm[3]
                            + sm[4] + sm[5] + sm[6] + sm[7];
        }
    }

    __shared__ int s_last;
    if (tid == 0) {
        __threadfence();
        int old = atomicAdd(&g_done, 1);
        s_last = (old == 2 * NACT - 1) ? 1 : 0;
        if (s_last) g_done = 0;
    }
    __syncthreads();
    if (!s_last) return;
    __threadfence();

    __shared__ float sl[NACT];
    if (tid < 32) {
        const int lane = tid;
        float l0 = g_part[0][lane]      + g_part[1][lane]      + hb[lane];
        float l1 = g_part[0][lane + 32] + g_part[1][lane + 32] + hb[lane + 32];
        sl[lane] = l0;
        sl[lane + 32] = l1;

        uint32_t kk0, kk1;
        threefry2x32(0u, 42u, 0u, (uint32_t)t, kk0, kk1);
        uint32_t a0, a1, b0, b1;
        threefry2x32(kk0, kk1, 0u, (uint32_t)lane,        a0, a1);
        threefry2x32(kk0, kk1, 0u, (uint32_t)(lane + 32), b0, b1);
        float u0 = jax_uniform(a0 ^ a1);
        float u1 = jax_uniform(b0 ^ b1);
        float gum0 = -logf(-logf(u0));
        float gum1 = -logf(-logf(u1));

        float v0 = l0 + gum0;
        float v1 = l1 + gum1;

        float bestv; int besti;
        if (v1 > v0) { bestv = v1; besti = lane + 32; }
        else         { bestv = v0; besti = lane; }
#pragma unroll
        for (int o = 16; o; o >>= 1) {
            float ov = __shfl_xor_sync(0xffffffffu, bestv, o);
            int   oi = __shfl_xor_sync(0xffffffffu, besti, o);
            if (ov > bestv || (ov == bestv && oi < besti)) { bestv = ov; besti = oi; }
        }
        float mx = fmaxf(l0, l1);
#pragma unroll
        for (int o = 16; o; o >>= 1) mx = fmaxf(mx, __shfl_xor_sync(0xffffffffu, mx, o));
        float se = expf(l0 - mx) + expf(l1 - mx);
#pragma unroll
        for (int o = 16; o; o >>= 1) se += __shfl_xor_sync(0xffffffffu, se, o);

        if (lane == 0) {
            float logp = (sl[besti] - mx) - logf(se);
            float news = g_logp_sum + logp;
            g_logp_sum = news;
            g_action   = besti;
            out[t] = (float)besti;
            if (t == STEPS - 1 && out_size > STEPS) out[STEPS] = news;
        }
    }
    __syncthreads();
    int a = g_action;
    const float* src = action_emb + (size_t)a * H;
    for (int k = tid; k < H; k += 256) g_x[k] = src[k];
}

// ---------------- launch ----------------
extern "C" void kernel_launch(void* const* d_in, const int* in_sizes, int n_in,
                              void* d_out, int out_size) {
    const float* start_token = (const float*)d_in[0];
    const float* action_emb  = (const float*)d_in[1];
    const float* w_ih        = (const float*)d_in[2];
    const float* w_hh        = (const float*)d_in[3];
    const float* b_ih        = (const float*)d_in[4];
    const float* b_hh        = (const float*)d_in[5];
    const float* head_w      = (const float*)d_in[6];
    const float* head_b      = (const float*)d_in[7];
    float* out = (float*)d_out;

    cudaFuncSetAttribute(cell_kernel,
                         cudaFuncAttributeMaxDynamicSharedMemorySize, CELL_DSM);

    convert_kernel<<<4096, 256>>>(w_ih, w_hh);
    init_kernel<<<(H + 255) / 256, 256>>>(start_token);

    for (int t = 0; t < STEPS; t++) {
        for (int l = 0; l < NLAYERS; l++) {
            cell_kernel<<<512, 256, CELL_DSM>>>(b_ih + (size_t)l * 4 * H,
                                                b_hh + (size_t)l * 4 * H,
                                                l, t);
        }
        head_sample_kernel<<<2 * NACT, 256>>>(head_w + (size_t)t * NACT * H,
                                              head_b + (size_t)t * NACT,
                                              action_emb, t, out, out_size);
    }
}

// round 17
// speedup vs baseline: 1.3511x; 1.3511x over previous
#include <cuda_runtime.h>
#include <cuda_bf16.h>
#include <cstdint>
#include <cstddef>

#define H 2048
#define NACT 64
#define STEPS 32
#define NLAYERS 2

// ---------------- device state ----------------
__device__ __align__(16) float g_h[2][NLAYERS][H];   // [parity][layer]
__device__ __align__(16) float g_c[NLAYERS][H];
__device__ __align__(16) float g_x[H];
__device__ __align__(16) float g_part[2][NACT];      // head partial dots
__device__ float g_logp_sum;
__device__ int   g_action;
__device__ int   g_done;

// dynamic vector maxabs (fp32 bits, monotone under uint atomicMax).
// g_vmax_x[t]: maxabs of layer-0 input token at step t (init writes 0, sample t writes t+1)
// g_vmax_h[t][l]: maxabs of h state written at "time t" (init zeroes t=0; cell(t,l) writes t+1)
__device__ uint32_t g_vmax_x[STEPS + 1];
__device__ uint32_t g_vmax_h[STEPS + 1][NLAYERS];

// per-row weight scales: [layer][half(0=ih,1=hh)][row'] with row' = j*4+gate
__device__ float g_wscale[NLAYERS][2][4 * H];

// int8 weights, IMMA-fragment-ready:
// tile T (0..511) covers rows' 16T..16T+15 (row' = j*4+gate) over concat-K 4096
// (k<2048: W_ih, else W_hh). Tile = 64 KB contiguous. chunk c (0..127) = k32.
// 16B unit at (c*512 + lane*16): a0 = row gid, k 32c+4t4..+3; a1 = row gid+8 same k;
// a2 = row gid, k 32c+16+4t4..+3; a3 = row gid+8 same. (bf16 m16n8k16 layout x2,
// validated R9.) Stage s = chunks 16s..16s+15 = 8 KB.
__device__ __align__(16) unsigned char g_wq[(size_t)NLAYERS * 512 * 65536];

// ---------------- threefry2x32-20 (bit-exact JAX core) ----------------
__device__ __forceinline__ uint32_t rotl32(uint32_t v, int d) {
    return (v << d) | (v >> (32 - d));
}
__device__ __forceinline__ void threefry2x32(uint32_t k0, uint32_t k1,
                                             uint32_t x0, uint32_t x1,
                                             uint32_t& o0, uint32_t& o1) {
    const uint32_t ks2 = k0 ^ k1 ^ 0x1BD11BDAu;
    x0 += k0; x1 += k1;
    x0 += x1; x1 = rotl32(x1, 13); x1 ^= x0;
    x0 += x1; x1 = rotl32(x1, 15); x1 ^= x0;
    x0 += x1; x1 = rotl32(x1, 26); x1 ^= x0;
    x0 += x1; x1 = rotl32(x1, 6);  x1 ^= x0;
    x0 += k1; x1 += ks2 + 1u;
    x0 += x1; x1 = rotl32(x1, 17); x1 ^= x0;
    x0 += x1; x1 = rotl32(x1, 29); x1 ^= x0;
    x0 += x1; x1 = rotl32(x1, 16); x1 ^= x0;
    x0 += x1; x1 = rotl32(x1, 24); x1 ^= x0;
    x0 += ks2; x1 += k0 + 2u;
    x0 += x1; x1 = rotl32(x1, 13); x1 ^= x0;
    x0 += x1; x1 = rotl32(x1, 15); x1 ^= x0;
    x0 += x1; x1 = rotl32(x1, 26); x1 ^= x0;
    x0 += x1; x1 = rotl32(x1, 6);  x1 ^= x0;
    x0 += k0; x1 += k1 + 3u;
    x0 += x1; x1 = rotl32(x1, 17); x1 ^= x0;
    x0 += x1; x1 = rotl32(x1, 29); x1 ^= x0;
    x0 += x1; x1 = rotl32(x1, 16); x1 ^= x0;
    x0 += x1; x1 = rotl32(x1, 24); x1 ^= x0;
    x0 += k1; x1 += ks2 + 4u;
    x0 += x1; x1 = rotl32(x1, 13); x1 ^= x0;
    x0 += x1; x1 = rotl32(x1, 15); x1 ^= x0;
    x0 += x1; x1 = rotl32(x1, 26); x1 ^= x0;
    x0 += x1; x1 = rotl32(x1, 6);  x1 ^= x0;
    x0 += ks2; x1 += k0 + 5u;
    o0 = x0; o1 = x1;
}
__device__ __forceinline__ float jax_uniform(uint32_t bits) {
    const float tiny = 1.1754943508222875e-38f;
    uint32_t fb = (bits >> 9) | 0x3f800000u;
    float u = __uint_as_float(fb) - 1.0f;
    u = u * 1.0f + tiny;
    return fmaxf(tiny, u);
}

__device__ __forceinline__ uint32_t pack_q8(float4 f, float inv) {
    int q0 = (int)rintf(f.x * inv);
    int q1 = (int)rintf(f.y * inv);
    int q2 = (int)rintf(f.z * inv);
    int q3 = (int)rintf(f.w * inv);
    return (uint32_t)(uint8_t)(int8_t)q0
         | ((uint32_t)(uint8_t)(int8_t)q1 << 8)
         | ((uint32_t)(uint8_t)(int8_t)q2 << 16)
         | ((uint32_t)(uint8_t)(int8_t)q3 << 24);
}

// ---------------- pass 1: per-row maxabs -> scales ----------------
// one warp per (l, half, row'): 32768 warps.
__global__ void scale_kernel(const float* __restrict__ w_ih,
                             const float* __restrict__ w_hh) {
    int wg   = blockIdx.x * 8 + (threadIdx.x >> 5);
    int lane = threadIdx.x & 31;
    int rp    = wg & 8191;
    int which = (wg >> 13) & 1;
    int l     = wg >> 14;
    int gate = rp & 3, j = rp >> 2;
    const float* W = (which ? w_hh : w_ih) + (size_t)l * 4 * H * H
                   + ((size_t)gate * H + j) * H;
    float m = 0.f;
    for (int i = lane; i < H; i += 32) m = fmaxf(m, fabsf(W[i]));
#pragma unroll
    for (int o = 16; o; o >>= 1) m = fmaxf(m, __shfl_xor_sync(0xffffffffu, m, o));
    if (lane == 0) g_wscale[l][which][rp] = fmaxf(m, 1e-30f) / 127.f;
}

// ---------------- pass 2: quantize into IMMA fragment layout ----------------
__global__ void quant_kernel(const float* __restrict__ w_ih,
                             const float* __restrict__ w_hh) {
    const size_t NU = (size_t)NLAYERS * 512 * 128 * 32;   // 16B units
    size_t stride = (size_t)gridDim.x * blockDim.x;
    for (size_t u = (size_t)blockIdx.x * blockDim.x + threadIdx.x; u < NU; u += stride) {
        int lane = (int)(u & 31);
        int c    = (int)((u >> 5) & 127);
        int T    = (int)((u >> 12) & 511);
        int l    = (int)(u >> 21);
        int gid  = lane >> 2, t4 = lane & 3;
        int k0c  = 32 * c + 4 * t4;            // concat-k
        int which = k0c >> 11;
        int kk   = k0c & 2047;
        const float* W = (which ? w_hh : w_ih) + (size_t)l * 4 * H * H;
        int r0 = 16 * T + gid, r1 = r0 + 8;
        const float* r0p = W + ((size_t)(r0 & 3) * H + (r0 >> 2)) * H;
        const float* r1p = W + ((size_t)(r1 & 3) * H + (r1 >> 2)) * H;
        float inv0 = 1.f / g_wscale[l][which][r0 & 8191];
        float inv1 = 1.f / g_wscale[l][which][r1 & 8191];
        uint4 o;
        o.x = pack_q8(*reinterpret_cast<const float4*>(r0p + kk),      inv0);
        o.y = pack_q8(*reinterpret_cast<const float4*>(r1p + kk),      inv1);
        o.z = pack_q8(*reinterpret_cast<const float4*>(r0p + kk + 16), inv0);
        o.w = pack_q8(*reinterpret_cast<const float4*>(r1p + kk + 16), inv1);
        reinterpret_cast<uint4*>(g_wq)[u] = o;
    }
}

// ---------------- init ----------------
__global__ void init_kernel(const float* __restrict__ start_token) {
    int i = blockIdx.x * blockDim.x + threadIdx.x;
    if (i < H) {
        float v = start_token[i];
        g_x[i] = v;
        g_c[0][i] = 0.f; g_c[1][i] = 0.f;
        g_h[0][0][i] = 0.f; g_h[0][1][i] = 0.f;
        g_h[1][0][i] = 0.f; g_h[1][1][i] = 0.f;
        // token maxabs -> slot 0 (atomicMax idempotent across replays)
        float m = fabsf(v);
#pragma unroll
        for (int o = 16; o; o >>= 1) m = fmaxf(m, __shfl_xor_sync(0xffffffffu, m, o));
        if ((i & 31) == 0) atomicMax(&g_vmax_x[0], __float_as_uint(m));
        if (i <= STEPS) { g_vmax_h[i][0] = 0u; g_vmax_h[i][1] = 0u; }
        if (i == 0) { g_logp_sum = 0.f; g_action = 0; g_done = 0; }
    }
}

#define CP_ASYNC_16(smem_u32, gptr) \
    asm volatile("cp.async.cg.shared.global [%0], [%1], 16;" \
                 :: "r"(smem_u32), "l"(gptr) : "memory")
#define CP_COMMIT() asm volatile("cp.async.commit_group;" ::: "memory")

#define IMMA(d0, d1, d2, d3, a, b0, b1) \
    asm volatile( \
        "mma.sync.aligned.m16n8k32.row.col.s32.s8.s8.s32 " \
        "{%0,%1,%2,%3}, {%4,%5,%6,%7}, {%8,%9}, {%0,%1,%2,%3};" \
        : "+r"(d0), "+r"(d1), "+r"(d2), "+r"(d3) \
        : "r"((a).x), "r"((a).y), "r"((a).z), "r"((a).w), "r"(b0), "r"(b1))

// ---------------- int8 IMMA LSTM cell, cp.async 4-deep ring ----------------
// grid = 512 blocks x 256 threads (8 warps). Block = tile T (16 rows' = 4 j x
// 4 gates, concat K=4096 = 64 KB int8). 8 stages x 8 KB, 4-slot static ring.
// Stages 0-3 accumulate ih half (scale wscale_ih*vsx), 4-7 hh half.
// Cross-warp reduce in exact int32; 4 threads fuse gates.
__global__ void __launch_bounds__(256)
cell_kernel(const float* __restrict__ bih, const float* __restrict__ bhh,
            int layer, int t) {
    __shared__ __align__(16) unsigned char ring[4][8192];
    __shared__ __align__(16) int8_t sv8[4096];
    __shared__ int spih[8][16], sphh[8][16];
    __shared__ float sh4[4];
    const int tid  = threadIdx.x;
    const int wid  = tid >> 5;
    const int lane = tid & 31;
    const int t4   = lane & 3, gid = lane >> 2;
    const int par_in  = t & 1;
    const int par_out = (t + 1) & 1;
    const int T = blockIdx.x;

    const unsigned char* wt = g_wq + (size_t)(layer * 512 + T) * 65536;

    // prologue: stages 0..2 in flight
#pragma unroll
    for (int p = 0; p < 3; p++) {
        uint32_t sp = (uint32_t)__cvta_generic_to_shared(&ring[p][tid * 16]);
        const unsigned char* gp = wt + (size_t)p * 8192 + tid * 16;
        CP_ASYNC_16(sp, gp);
        CP_ASYNC_16(sp + 4096, gp + 4096);
        CP_COMMIT();
    }

    // vector scales
    uint32_t xb = (layer == 0) ? g_vmax_x[t] : g_vmax_h[t + 1][0];
    uint32_t hbits = g_vmax_h[t][layer];
    float xm = __uint_as_float(xb), hm = __uint_as_float(hbits);
    float invx = (xm > 0.f) ? 127.f / xm : 0.f;
    float invh = (hm > 0.f) ? 127.f / hm : 0.f;

    // quantize concat vector into smem (16 elements per thread)
    {
        const float* vx = (layer == 0) ? g_x : g_h[par_out][0];
        const float* vh = g_h[par_in][layer];
        int e0 = tid * 16;
        const float* src = (e0 < 2048) ? vx + e0 : vh + (e0 - 2048);
        float inv = (e0 < 2048) ? invx : invh;
        uint4 o;
        o.x = pack_q8(*reinterpret_cast<const float4*>(src),      inv);
        o.y = pack_q8(*reinterpret_cast<const float4*>(src + 4),  inv);
        o.z = pack_q8(*reinterpret_cast<const float4*>(src + 8),  inv);
        o.w = pack_q8(*reinterpret_cast<const float4*>(src + 12), inv);
        *reinterpret_cast<uint4*>(sv8 + e0) = o;
    }

    int ih0 = 0, ih1 = 0, ih2 = 0, ih3 = 0;
    int hh0 = 0, hh1 = 0, hh2 = 0, hh3 = 0;

    for (int s = 0; s < 8; s++) {
        if (s <= 5)      asm volatile("cp.async.wait_group 2;" ::: "memory");
        else if (s == 6) asm volatile("cp.async.wait_group 1;" ::: "memory");
        else             asm volatile("cp.async.wait_group 0;" ::: "memory");
        __syncthreads();   // stage s (and sv8 on s=0) visible

        const unsigned char* buf = ring[s & 3];
        if (s < 4) {
#pragma unroll
            for (int i = 0; i < 2; i++) {
                int q = 2 * wid + i;
                int c = s * 16 + q;
                uint4 a = *reinterpret_cast<const uint4*>(buf + q * 512 + lane * 16);
                uint32_t b0 = *reinterpret_cast<const uint32_t*>(sv8 + 32 * c + 4 * t4);
                uint32_t b1 = *reinterpret_cast<const uint32_t*>(sv8 + 32 * c + 16 + 4 * t4);
                IMMA(ih0, ih1, ih2, ih3, a, b0, b1);
            }
        } else {
#pragma unroll
            for (int i = 0; i < 2; i++) {
                int q = 2 * wid + i;
                int c = s * 16 + q;
                uint4 a = *reinterpret_cast<const uint4*>(buf + q * 512 + lane * 16);
                uint32_t b0 = *reinterpret_cast<const uint32_t*>(sv8 + 32 * c + 4 * t4);
                uint32_t b1 = *reinterpret_cast<const uint32_t*>(sv8 + 32 * c + 16 + 4 * t4);
                IMMA(hh0, hh1, hh2, hh3, a, b0, b1);
            }
        }
        __syncthreads();   // slot consumed before refill

        if (s + 3 < 8) {
            int p = s + 3;
            uint32_t sp = (uint32_t)__cvta_generic_to_shared(&ring[p & 3][tid * 16]);
            const unsigned char* gp = wt + (size_t)p * 8192 + tid * 16;
            CP_ASYNC_16(sp, gp);
            CP_ASYNC_16(sp + 4096, gp + 4096);
            CP_COMMIT();
        }
    }

    // c0 -> row' gid, c2 -> row' gid+8 (cols identical)
    if (t4 == 0) {
        spih[wid][gid]     = ih0;
        spih[wid][gid + 8] = ih2;
        sphh[wid][gid]     = hh0;
        sphh[wid][gid + 8] = hh2;
    }
    __syncthreads();

    if (tid < 4) {
        const int j = 4 * T + tid;
        const float vsx = xm / 127.f, vsh = hm / 127.f;
        float gate[4];
#pragma unroll
        for (int gt = 0; gt < 4; gt++) {
            const int rl = tid * 4 + gt;
            int si = 0, sh_ = 0;
#pragma unroll
            for (int w = 0; w < 8; w++) { si += spih[w][rl]; sh_ += sphh[w][rl]; }
            float fih = (float)si  * (g_wscale[layer][0][16 * T + rl] * vsx);
            float fhh = (float)sh_ * (g_wscale[layer][1][16 * T + rl] * vsh);
            gate[gt] = fih + fhh + bih[gt * H + j] + bhh[gt * H + j];
        }
        float i_ = 1.0f / (1.0f + expf(-gate[0]));
        float f_ = 1.0f / (1.0f + expf(-gate[1]));
        float g_ = tanhf(gate[2]);
        float o_ = 1.0f / (1.0f + expf(-gate[3]));
        float cn = f_ * g_c[layer][j] + i_ * g_;
        g_c[layer][j] = cn;
        float hn = o_ * tanhf(cn);
        g_h[par_out][layer][j] = hn;
        sh4[tid] = fabsf(hn);
    }
    __syncthreads();
    if (tid == 0) {
        float m = fmaxf(fmaxf(sh4[0], sh4[1]), fmaxf(sh4[2], sh4[3]));
        atomicMax(&g_vmax_h[t + 1][layer], __float_as_uint(m));
    }
}

// ---------------- fused head + sample (fp32, unchanged numerics) ----------------
__global__ void __launch_bounds__(256)
head_sample_kernel(const float* __restrict__ hw, const float* __restrict__ hb,
                   const float* __restrict__ action_emb,
                   int t, float* __restrict__ out, int out_size) {
    const int r    = blockIdx.x & (NACT - 1);
    const int half = blockIdx.x >> 6;
    const int tid  = threadIdx.x;
    const int par_out = (t + 1) & 1;

    {
        const float4* row = reinterpret_cast<const float4*>(hw + (size_t)r * H);
        const float4* v4  = reinterpret_cast<const float4*>(g_h[par_out][1]);
        int k = half * 256 + tid;
        float4 a = row[k];
        float4 b = v4[k];
        float s = a.x * b.x + a.y * b.y + a.z * b.z + a.w * b.w;
#pragma unroll
        for (int o = 16; o; o >>= 1) s += __shfl_xor_sync(0xffffffffu, s, o);
        __shared__ float sm[8];
        if ((tid & 31) == 0) sm[tid >> 5] = s;
        __syncthreads();
        if (tid == 0) {
            g_part[half][r] = sm[0] + sm[1] + sm[2] + sm[3]
                            + sm[4] + sm[5] + sm[6] + sm[7];
        }
    }

    __shared__ int s_last;
    if (tid == 0) {
        __threadfence();
        int old = atomicAdd(&g_done, 1);
        s_last = (old == 2 * NACT - 1) ? 1 : 0;
        if (s_last) g_done = 0;
    }
    __syncthreads();
    if (!s_last) return;
    __threadfence();

    __shared__ float sl[NACT];
    if (tid < 32) {
        const int lane = tid;
        float l0 = g_part[0][lane]      + g_part[1][lane]      + hb[lane];
        float l1 = g_part[0][lane + 32] + g_part[1][lane + 32] + hb[lane + 32];
        sl[lane] = l0;
        sl[lane + 32] = l1;

        uint32_t kk0, kk1;
        threefry2x32(0u, 42u, 0u, (uint32_t)t, kk0, kk1);
        uint32_t a0, a1, b0, b1;
        threefry2x32(kk0, kk1, 0u, (uint32_t)lane,        a0, a1);
        threefry2x32(kk0, kk1, 0u, (uint32_t)(lane + 32), b0, b1);
        float u0 = jax_uniform(a0 ^ a1);
        float u1 = jax_uniform(b0 ^ b1);
        float gum0 = -logf(-logf(u0));
        float gum1 = -logf(-logf(u1));

        float v0 = l0 + gum0;
        float v1 = l1 + gum1;

        float bestv; int besti;
        if (v1 > v0) { bestv = v1; besti = lane + 32; }
        else         { bestv = v0; besti = lane; }
#pragma unroll
        for (int o = 16; o; o >>= 1) {
            float ov = __shfl_xor_sync(0xffffffffu, bestv, o);
            int   oi = __shfl_xor_sync(0xffffffffu, besti, o);
            if (ov > bestv || (ov == bestv && oi < besti)) { bestv = ov; besti = oi; }
        }
        float mx = fmaxf(l0, l1);
#pragma unroll
        for (int o = 16; o; o >>= 1) mx = fmaxf(mx, __shfl_xor_sync(0xffffffffu, mx, o));
        float se = expf(l0 - mx) + expf(l1 - mx);
#pragma unroll
        for (int o = 16; o; o >>= 1) se += __shfl_xor_sync(0xffffffffu, se, o);

        if (lane == 0) {
            float logp = (sl[besti] - mx) - logf(se);
            float news = g_logp_sum + logp;
            g_logp_sum = news;
            g_action   = besti;
            out[t] = (float)besti;
            if (t == STEPS - 1 && out_size > STEPS) out[STEPS] = news;
        }
    }
    __syncthreads();

    // copy next embedding + its maxabs -> g_vmax_x[t+1]
    int a = g_action;
    const float* src = action_emb + (size_t)a * H;
    float lm = 0.f;
    for (int k = tid; k < H; k += 256) {
        float v = src[k];
        g_x[k] = v;
        lm = fmaxf(lm, fabsf(v));
    }
#pragma unroll
    for (int o = 16; o; o >>= 1) lm = fmaxf(lm, __shfl_xor_sync(0xffffffffu, lm, o));
    __shared__ float smx[8];
    if ((tid & 31) == 0) smx[tid >> 5] = lm;
    __syncthreads();
    if (tid == 0) {
        float m = 0.f;
#pragma unroll
        for (int w = 0; w < 8; w++) m = fmaxf(m, smx[w]);
        g_vmax_x[t + 1] = __float_as_uint(m);
    }
}

// ---------------- launch ----------------
extern "C" void kernel_launch(void* const* d_in, const int* in_sizes, int n_in,
                              void* d_out, int out_size) {
    const float* start_token = (const float*)d_in[0];
    const float* action_emb  = (const float*)d_in[1];
    const float* w_ih        = (const float*)d_in[2];
    const float* w_hh        = (const float*)d_in[3];
    const float* b_ih        = (const float*)d_in[4];
    const float* b_hh        = (const float*)d_in[5];
    const float* head_w      = (const float*)d_in[6];
    const float* head_b      = (const float*)d_in[7];
    float* out = (float*)d_out;

    scale_kernel<<<4096, 256>>>(w_ih, w_hh);
    quant_kernel<<<4096, 256>>>(w_ih, w_hh);
    init_kernel<<<(H + 255) / 256, 256>>>(start_token);

    for (int t = 0; t < STEPS; t++) {
        for (int l = 0; l < NLAYERS; l++) {
            cell_kernel<<<512, 256>>>(b_ih + (size_t)l * 4 * H,
                                      b_hh + (size_t)l * 4 * H,
                                      l, t);
        }
        head_sample_kernel<<<2 * NACT, 256>>>(head_w + (size_t)t * NACT * H,
                                              head_b + (size_t)t * NACT,
                                              action_emb, t, out, out_size);
    }
}